// round 1
// baseline (speedup 1.0000x reference)
#include <cuda_runtime.h>

#define N_NODES 10000
#define N_EDGES 160000
#define E_TOT   (N_EDGES + N_NODES)
#define DIM     256
#define HEADS   8
#define CH      32
#define LORA_SCALE 4.0f
#define ATT_SCALE  8.0f
#define NEG_SLOPE  0.2f

// ---------------- device scratch (static: no allocations allowed) ----------------
__device__ float g_weff[DIM * DIM];
__device__ float g_atts[DIM];            // effective att_src vector [H*C]
__device__ float g_attd[DIM];            // effective att_dst vector [H*C]
__device__ float g_xp[N_NODES * DIM];    // projected features (per layer)
__device__ float g_act[N_NODES * DIM];   // aggregated output / elu'd activations
__device__ float g_ssrc[N_NODES * HEADS];
__device__ float g_sdst[N_NODES * HEADS];
__device__ int   g_deg[N_NODES];
__device__ int   g_off[N_NODES + 1];
__device__ int   g_cur[N_NODES];
__device__ int   g_csrc[E_TOT];
__device__ int   g_flag64;               // OR of high words; 0 => int64 input

// ---------------- edge dtype handling ----------------
__device__ __forceinline__ int edge_val(const void* ei, long long idx, int is64) {
    if (is64) return (int)((const long long*)ei)[idx];
    return ((const int*)ei)[idx];
}

__global__ void k_init() {
    int n = blockIdx.x * blockDim.x + threadIdx.x;
    if (n == 0) g_flag64 = 0;
    if (n < N_NODES) g_deg[n] = 1;   // self loop pre-counted
}

// OR-reduce odd 32-bit words of the first N_EDGES entries.
// If the buffer is int64, those words are the (always-zero) high halves.
__global__ void k_detect(const void* ei) {
    const int* w = (const int*)ei;
    int acc = 0;
    for (int i = blockIdx.x * blockDim.x + threadIdx.x; i < N_EDGES; i += gridDim.x * blockDim.x)
        acc |= w[2 * i + 1];
    // warp-reduce then atomic
    for (int o = 16; o; o >>= 1) acc |= __shfl_xor_sync(0xffffffffu, acc, o);
    if ((threadIdx.x & 31) == 0 && acc) atomicOr(&g_flag64, acc);
}

__global__ void k_hist(const void* ei) {
    int is64 = (g_flag64 == 0);
    int e = blockIdx.x * blockDim.x + threadIdx.x;
    if (e < N_EDGES) {
        int d = edge_val(ei, (long long)N_EDGES + e, is64);
        atomicAdd(&g_deg[d], 1);
    }
}

// single block, 512 threads, 20 nodes per thread: exclusive scan of degrees
__global__ void k_scan() {
    __shared__ int s[512];
    int t = threadIdx.x;
    int base = t * 20;
    int loc[20];
    int sum = 0;
#pragma unroll
    for (int i = 0; i < 20; i++) {
        int n = base + i;
        int d = (n < N_NODES) ? g_deg[n] : 0;
        loc[i] = sum;
        sum += d;
    }
    s[t] = sum;
    __syncthreads();
    for (int off = 1; off < 512; off <<= 1) {
        int v = 0;
        if (t >= off) v = s[t - off];
        __syncthreads();
        if (t >= off) s[t] += v;
        __syncthreads();
    }
    int excl = s[t] - sum;
#pragma unroll
    for (int i = 0; i < 20; i++) {
        int n = base + i;
        if (n <= N_NODES) {
            int o = excl + loc[i];
            g_off[n] = o;
            if (n < N_NODES) g_cur[n] = o;
        }
    }
}

__global__ void k_scatter(const void* ei) {
    int is64 = (g_flag64 == 0);
    int e = blockIdx.x * blockDim.x + threadIdx.x;
    if (e < N_EDGES) {
        int s = edge_val(ei, e, is64);
        int d = edge_val(ei, (long long)N_EDGES + e, is64);
        int pos = atomicAdd(&g_cur[d], 1);
        g_csrc[pos] = s;
    } else if (e < E_TOT) {
        int n = e - N_EDGES;
        int pos = atomicAdd(&g_cur[n], 1);
        g_csrc[pos] = n;
    }
}

// ---------------- weight folding ----------------
// W_eff[o][i] = W[o][i] + LORA_SCALE * sum_r B[o][r] * A[r][i]
__global__ void k_build_weff(const float* __restrict__ W, const float* __restrict__ A,
                             const float* __restrict__ B) {
    int o = blockIdx.x, i = threadIdx.x;
    float s = 0.f;
#pragma unroll
    for (int r = 0; r < 8; r++) s += B[o * 8 + r] * A[r * DIM + i];
    g_weff[o * DIM + i] = W[o * DIM + i] + LORA_SCALE * s;
}

// att_eff[h][c] = att[h][c] + ATT_SCALE * sum_r Ba[r] * Aa[r][c]
__global__ void k_build_att(const float* __restrict__ as_, const float* __restrict__ ad_,
                            const float* __restrict__ As, const float* __restrict__ Bs,
                            const float* __restrict__ Ad, const float* __restrict__ Bd) {
    int t = threadIdx.x;          // h*32+c
    int c = t & 31;
    float ss = 0.f, sd = 0.f;
#pragma unroll
    for (int r = 0; r < 4; r++) {
        ss += Bs[r] * As[r * CH + c];
        sd += Bd[r] * Ad[r * CH + c];
    }
    g_atts[t] = as_[t] + ATT_SCALE * ss;
    g_attd[t] = ad_[t] + ATT_SCALE * sd;
}

// ---------------- GEMM: Y[m][n] = sum_k X[m][k] * g_weff[n][k] ----------------
// M=10000, N=256, K=256. 64x64 block tile, BK=16, 256 threads, 4x4 per thread.
__global__ void __launch_bounds__(256) k_gemm(const float* __restrict__ X, float* __restrict__ Y) {
    __shared__ __align__(16) float As[16][68];
    __shared__ __align__(16) float Bs[16][68];
    int m0 = blockIdx.y * 64, n0 = blockIdx.x * 64;
    int t = threadIdx.x;
    int lrow = t >> 2, lseg = t & 3;
    int tx = t & 15, ty = t >> 4;
    float acc[4][4] = {};

    for (int k0 = 0; k0 < DIM; k0 += 16) {
        int gm = m0 + lrow;
        float4 va = make_float4(0.f, 0.f, 0.f, 0.f);
        if (gm < N_NODES) va = *(const float4*)(X + (long long)gm * DIM + k0 + lseg * 4);
        As[lseg * 4 + 0][lrow] = va.x;
        As[lseg * 4 + 1][lrow] = va.y;
        As[lseg * 4 + 2][lrow] = va.z;
        As[lseg * 4 + 3][lrow] = va.w;
        float4 vb = *(const float4*)(g_weff + (n0 + lrow) * DIM + k0 + lseg * 4);
        Bs[lseg * 4 + 0][lrow] = vb.x;
        Bs[lseg * 4 + 1][lrow] = vb.y;
        Bs[lseg * 4 + 2][lrow] = vb.z;
        Bs[lseg * 4 + 3][lrow] = vb.w;
        __syncthreads();
#pragma unroll
        for (int k = 0; k < 16; k++) {
            float4 a = *(const float4*)&As[k][ty * 4];
            float4 b = *(const float4*)&Bs[k][tx * 4];
            float av[4] = {a.x, a.y, a.z, a.w};
            float bv[4] = {b.x, b.y, b.z, b.w};
#pragma unroll
            for (int i = 0; i < 4; i++)
#pragma unroll
                for (int j = 0; j < 4; j++) acc[i][j] += av[i] * bv[j];
        }
        __syncthreads();
    }
#pragma unroll
    for (int i = 0; i < 4; i++) {
        int gm = m0 + ty * 4 + i;
        if (gm < N_NODES) {
#pragma unroll
            for (int j = 0; j < 4; j++) Y[(long long)gm * DIM + n0 + tx * 4 + j] = acc[i][j];
        }
    }
}

// ---------------- per-node attention scores ----------------
__global__ void k_scores(const float* __restrict__ xp) {
    int n = blockIdx.x;
    int t = threadIdx.x;
    int h = t >> 5, lane = t & 31;
    float v = xp[n * DIM + t];
    float ps = v * g_atts[t];
    float pd = v * g_attd[t];
#pragma unroll
    for (int o = 16; o; o >>= 1) {
        ps += __shfl_down_sync(0xffffffffu, ps, o);
        pd += __shfl_down_sync(0xffffffffu, pd, o);
    }
    if (lane == 0) {
        g_ssrc[n * HEADS + h] = ps;
        g_sdst[n * HEADS + h] = pd;
    }
}

// ---------------- segment softmax + aggregation (block per node, warp per head) --
template <bool ELU>
__global__ void __launch_bounds__(256) k_aggr(const float* __restrict__ xp, float* __restrict__ out) {
    int n = blockIdx.x;
    int t = threadIdx.x;
    int h = t >> 5, lane = t & 31;
    int beg = g_off[n], end = g_off[n + 1];
    float ssrc = g_ssrc[n * HEADS + h];

    // pass 1a: max over edges
    float m = -1e30f;
    for (int i = beg + lane; i < end; i += 32) {
        int s = g_csrc[i];
        float a = ssrc + g_sdst[s * HEADS + h];
        a = fmaxf(a, NEG_SLOPE * a);
        m = fmaxf(m, a);
    }
#pragma unroll
    for (int o = 16; o; o >>= 1) m = fmaxf(m, __shfl_xor_sync(0xffffffffu, m, o));

    // pass 1b: denominator
    float den = 0.f;
    for (int i = beg + lane; i < end; i += 32) {
        int s = g_csrc[i];
        float a = ssrc + g_sdst[s * HEADS + h];
        a = fmaxf(a, NEG_SLOPE * a);
        den += __expf(a - m);
    }
#pragma unroll
    for (int o = 16; o; o >>= 1) den += __shfl_xor_sync(0xffffffffu, den, o);
    float inv = 1.0f / den;

    // pass 2: weighted feature aggregation, lane = channel
    float acc = 0.f;
    for (int i = beg; i < end; i++) {
        int s = g_csrc[i];  // broadcast load
        float a = ssrc + g_sdst[s * HEADS + h];
        a = fmaxf(a, NEG_SLOPE * a);
        float w = __expf(a - m) * inv;
        acc += w * xp[s * DIM + h * CH + lane];
    }
    if (ELU) acc = (acc > 0.f) ? acc : (__expf(acc) - 1.0f);
    out[n * DIM + t] = acc;
}

// ---------------- head mean for final output ----------------
__global__ void k_mean(const float* __restrict__ agg, float* __restrict__ out) {
    int i = blockIdx.x * blockDim.x + threadIdx.x;
    if (i < N_NODES * CH) {
        int n = i >> 5, c = i & 31;
        float s = 0.f;
#pragma unroll
        for (int h = 0; h < HEADS; h++) s += agg[n * DIM + h * CH + c];
        out[i] = s * 0.125f;
    }
}

// ---------------- host launcher ----------------
extern "C" void kernel_launch(void* const* d_in, const int* in_sizes, int n_in,
                              void* d_out, int out_size) {
    const float* x  = (const float*)d_in[0];
    const void*  ei = d_in[1];

    float *xp, *act;
    cudaGetSymbolAddress((void**)&xp, g_xp);
    cudaGetSymbolAddress((void**)&act, g_act);

    // CSR build (shared by both layers)
    k_init<<<(N_NODES + 255) / 256, 256>>>();
    k_detect<<<64, 256>>>(ei);
    k_hist<<<(N_EDGES + 255) / 256, 256>>>(ei);
    k_scan<<<1, 512>>>();
    k_scatter<<<(E_TOT + 255) / 256, 256>>>(ei);

    dim3 gg(DIM / 64, (N_NODES + 63) / 64);

    // ---- layer 0 ----
    k_build_weff<<<DIM, DIM>>>((const float*)d_in[2], (const float*)d_in[3], (const float*)d_in[4]);
    k_build_att<<<1, DIM>>>((const float*)d_in[5], (const float*)d_in[6],
                            (const float*)d_in[7], (const float*)d_in[8],
                            (const float*)d_in[9], (const float*)d_in[10]);
    k_gemm<<<gg, 256>>>(x, xp);
    k_scores<<<N_NODES, 256>>>(xp);
    k_aggr<true><<<N_NODES, 256>>>(xp, act);

    // ---- layer 1 ----
    k_build_weff<<<DIM, DIM>>>((const float*)d_in[11], (const float*)d_in[12], (const float*)d_in[13]);
    k_build_att<<<1, DIM>>>((const float*)d_in[14], (const float*)d_in[15],
                            (const float*)d_in[16], (const float*)d_in[17],
                            (const float*)d_in[18], (const float*)d_in[19]);
    k_gemm<<<gg, 256>>>(act, xp);
    k_scores<<<N_NODES, 256>>>(xp);
    k_aggr<false><<<N_NODES, 256>>>(xp, act);

    k_mean<<<(N_NODES * CH + 255) / 256, 256>>>(act, (float*)d_out);
}

// round 3
// speedup vs baseline: 1.0043x; 1.0043x over previous
#include <cuda_runtime.h>

#define N_NODES 10000
#define N_EDGES 160000
#define E_TOT   (N_EDGES + N_NODES)
#define DIM     256
#define HEADS   8
#define CH      32
#define LORA_SCALE 4.0f
#define ATT_SCALE  8.0f
#define NEG_SLOPE  0.2f

// ---------------- device scratch ----------------
__device__ __align__(128) float g_weff[DIM * DIM];
__device__ __align__(128) float g_atts[DIM];
__device__ __align__(128) float g_attd[DIM];
__device__ __align__(128) float g_xp[N_NODES * DIM];
__device__ __align__(128) float g_act[N_NODES * DIM];
__device__ __align__(128) float g_ssrc[N_NODES * HEADS];
__device__ __align__(128) float g_sdst[N_NODES * HEADS];
__device__ int   g_deg[N_NODES];
__device__ int   g_off[N_NODES + 1];
__device__ int   g_cur[N_NODES];
__device__ int   g_csrc[E_TOT];
__device__ int   g_flag64;   // OR of odd words; stays 0 iff input is int64 (monotonic, no reset needed)

__device__ __forceinline__ int edge_val(const void* ei, long long idx, int is64) {
    if (is64) return (int)((const long long*)ei)[idx];
    return ((const int*)ei)[idx];
}

// ---------------- detect dtype + init degrees (self-loop pre-counted) ----------------
__global__ void k_detect(const void* ei) {
    int gid = blockIdx.x * blockDim.x + threadIdx.x;
    if (gid < N_NODES) g_deg[gid] = 1;
    const int* w = (const int*)ei;
    int acc = 0;
    for (int i = gid; i < N_EDGES; i += gridDim.x * blockDim.x) acc |= w[2 * i + 1];
#pragma unroll
    for (int o = 16; o; o >>= 1) acc |= __shfl_xor_sync(0xffffffffu, acc, o);
    if ((threadIdx.x & 31) == 0 && acc) atomicOr(&g_flag64, acc);
}

__global__ void k_hist(const void* ei) {
    int is64 = (g_flag64 == 0);
    int e = blockIdx.x * blockDim.x + threadIdx.x;
    if (e < N_EDGES) atomicAdd(&g_deg[edge_val(ei, (long long)N_EDGES + e, is64)], 1);
}

// 1024 threads, 10 nodes each: warp scan + cross-warp scan
__global__ void k_scan() {
    __shared__ int warp_sums[32];
    int t = threadIdx.x, lane = t & 31, w = t >> 5;
    int base = t * 10;
    int loc[10];
    int sum = 0;
#pragma unroll
    for (int i = 0; i < 10; i++) {
        int n = base + i;
        int d = (n < N_NODES) ? g_deg[n] : 0;
        loc[i] = sum;
        sum += d;
    }
    int v = sum;
#pragma unroll
    for (int o = 1; o < 32; o <<= 1) {
        int u = __shfl_up_sync(0xffffffffu, v, o);
        if (lane >= o) v += u;
    }
    if (lane == 31) warp_sums[w] = v;
    __syncthreads();
    if (w == 0) {
        int s = warp_sums[lane];
#pragma unroll
        for (int o = 1; o < 32; o <<= 1) {
            int u = __shfl_up_sync(0xffffffffu, s, o);
            if (lane >= o) s += u;
        }
        warp_sums[lane] = s;
    }
    __syncthreads();
    int excl = v - sum + (w ? warp_sums[w - 1] : 0);
#pragma unroll
    for (int i = 0; i < 10; i++) {
        int n = base + i;
        if (n < N_NODES) {
            int o = excl + loc[i];
            g_off[n] = o;
            g_cur[n] = o;
        }
    }
    if (t == 0) g_off[N_NODES] = E_TOT;
}

__global__ void k_scatter(const void* ei) {
    int is64 = (g_flag64 == 0);
    int e = blockIdx.x * blockDim.x + threadIdx.x;
    if (e < N_EDGES) {
        int s = edge_val(ei, e, is64);
        int d = edge_val(ei, (long long)N_EDGES + e, is64);
        g_csrc[atomicAdd(&g_cur[d], 1)] = s;
    } else if (e < E_TOT) {
        int n = e - N_EDGES;
        g_csrc[atomicAdd(&g_cur[n], 1)] = n;
    }
}

// ---------------- fold LoRA into effective weights (257 blocks) ----------------
__global__ void k_prep(const float* __restrict__ W, const float* __restrict__ A,
                       const float* __restrict__ B,
                       const float* __restrict__ as_, const float* __restrict__ ad_,
                       const float* __restrict__ As, const float* __restrict__ Bs,
                       const float* __restrict__ Ad, const float* __restrict__ Bd) {
    int b = blockIdx.x, t = threadIdx.x;
    if (b < DIM) {
        float s = 0.f;
#pragma unroll
        for (int r = 0; r < 8; r++) s += B[b * 8 + r] * A[r * DIM + t];
        g_weff[b * DIM + t] = W[b * DIM + t] + LORA_SCALE * s;
    } else {
        int c = t & 31;
        float ss = 0.f, sd = 0.f;
#pragma unroll
        for (int r = 0; r < 4; r++) {
            ss += Bs[r] * As[r * CH + c];
            sd += Bd[r] * Ad[r * CH + c];
        }
        g_atts[t] = as_[t] + ATT_SCALE * ss;
        g_attd[t] = ad_[t] + ATT_SCALE * sd;
    }
}

// ---------------- GEMM: Y[m][n] = sum_k X[m][k] * g_weff[n][k] ----------------
// 128x128 tile, BK=16, 256 threads, 8x8/thread, double-buffered smem, 1 sync/iter.
#define BM 128
#define BN 128
#define BK 16
__global__ void __launch_bounds__(256, 2) k_gemm(const float* __restrict__ X, float* __restrict__ Y) {
    __shared__ __align__(16) float As[2][BK][BM + 4];
    __shared__ __align__(16) float Bs[2][BK][BN + 4];
    const int t = threadIdx.x;
    const int m0 = blockIdx.y * BM, n0 = blockIdx.x * BN;
    const int r0 = t >> 2, r1 = (t + 256) >> 2;
    const int ks = (t & 3) * 4;
    const int tx = t & 15, ty = t >> 4;
    const int gm0 = m0 + r0, gm1 = m0 + r1;
    const float4 z4 = make_float4(0.f, 0.f, 0.f, 0.f);

    float acc[8][8] = {};
    float4 ra0, ra1, rb0, rb1;

    // prologue: tile 0 -> buffer 0
    ra0 = (gm0 < N_NODES) ? *(const float4*)(X + (size_t)gm0 * DIM + ks) : z4;
    ra1 = (gm1 < N_NODES) ? *(const float4*)(X + (size_t)gm1 * DIM + ks) : z4;
    rb0 = *(const float4*)(g_weff + (size_t)(n0 + r0) * DIM + ks);
    rb1 = *(const float4*)(g_weff + (size_t)(n0 + r1) * DIM + ks);
    As[0][ks + 0][r0] = ra0.x; As[0][ks + 1][r0] = ra0.y; As[0][ks + 2][r0] = ra0.z; As[0][ks + 3][r0] = ra0.w;
    As[0][ks + 0][r1] = ra1.x; As[0][ks + 1][r1] = ra1.y; As[0][ks + 2][r1] = ra1.z; As[0][ks + 3][r1] = ra1.w;
    Bs[0][ks + 0][r0] = rb0.x; Bs[0][ks + 1][r0] = rb0.y; Bs[0][ks + 2][r0] = rb0.z; Bs[0][ks + 3][r0] = rb0.w;
    Bs[0][ks + 0][r1] = rb1.x; Bs[0][ks + 1][r1] = rb1.y; Bs[0][ks + 2][r1] = rb1.z; Bs[0][ks + 3][r1] = rb1.w;
    __syncthreads();

    const int NIT = DIM / BK;
    for (int it = 0; it < NIT; it++) {
        int cur = it & 1, nxt = cur ^ 1;
        bool more = (it + 1 < NIT);
        if (more) {
            int k0 = (it + 1) * BK + ks;
            ra0 = (gm0 < N_NODES) ? *(const float4*)(X + (size_t)gm0 * DIM + k0) : z4;
            ra1 = (gm1 < N_NODES) ? *(const float4*)(X + (size_t)gm1 * DIM + k0) : z4;
            rb0 = *(const float4*)(g_weff + (size_t)(n0 + r0) * DIM + k0);
            rb1 = *(const float4*)(g_weff + (size_t)(n0 + r1) * DIM + k0);
        }
#pragma unroll
        for (int k = 0; k < BK; k++) {
            float4 x0 = *(const float4*)&As[cur][k][ty * 8];
            float4 x1 = *(const float4*)&As[cur][k][ty * 8 + 4];
            float4 y0 = *(const float4*)&Bs[cur][k][tx * 8];
            float4 y1 = *(const float4*)&Bs[cur][k][tx * 8 + 4];
            float av[8] = {x0.x, x0.y, x0.z, x0.w, x1.x, x1.y, x1.z, x1.w};
            float bv[8] = {y0.x, y0.y, y0.z, y0.w, y1.x, y1.y, y1.z, y1.w};
#pragma unroll
            for (int i = 0; i < 8; i++)
#pragma unroll
                for (int j = 0; j < 8; j++) acc[i][j] += av[i] * bv[j];
        }
        if (more) {
            As[nxt][ks + 0][r0] = ra0.x; As[nxt][ks + 1][r0] = ra0.y; As[nxt][ks + 2][r0] = ra0.z; As[nxt][ks + 3][r0] = ra0.w;
            As[nxt][ks + 0][r1] = ra1.x; As[nxt][ks + 1][r1] = ra1.y; As[nxt][ks + 2][r1] = ra1.z; As[nxt][ks + 3][r1] = ra1.w;
            Bs[nxt][ks + 0][r0] = rb0.x; Bs[nxt][ks + 1][r0] = rb0.y; Bs[nxt][ks + 2][r0] = rb0.z; Bs[nxt][ks + 3][r0] = rb0.w;
            Bs[nxt][ks + 0][r1] = rb1.x; Bs[nxt][ks + 1][r1] = rb1.y; Bs[nxt][ks + 2][r1] = rb1.z; Bs[nxt][ks + 3][r1] = rb1.w;
        }
        __syncthreads();
    }

#pragma unroll
    for (int i = 0; i < 8; i++) {
        int gm = m0 + ty * 8 + i;
        if (gm < N_NODES) {
            float4 v0 = make_float4(acc[i][0], acc[i][1], acc[i][2], acc[i][3]);
            float4 v1 = make_float4(acc[i][4], acc[i][5], acc[i][6], acc[i][7]);
            *(float4*)(Y + (size_t)gm * DIM + n0 + tx * 8) = v0;
            *(float4*)(Y + (size_t)gm * DIM + n0 + tx * 8 + 4) = v1;
        }
    }
}

// ---------------- per-node attention scores ----------------
__global__ void k_scores(const float* __restrict__ xp) {
    int n = blockIdx.x, t = threadIdx.x;
    int h = t >> 5, lane = t & 31;
    float v = xp[n * DIM + t];
    float ps = v * g_atts[t];
    float pd = v * g_attd[t];
#pragma unroll
    for (int o = 16; o; o >>= 1) {
        ps += __shfl_down_sync(0xffffffffu, ps, o);
        pd += __shfl_down_sync(0xffffffffu, pd, o);
    }
    if (lane == 0) {
        g_ssrc[n * HEADS + h] = ps;
        g_sdst[n * HEADS + h] = pd;
    }
}

// ---------------- single-pass softmax + aggregation ----------------
// MODE 0: ELU -> act[n*256 + t];  MODE 1: head-mean -> out[n*32 + lane]
template <int MODE>
__global__ void __launch_bounds__(256) k_aggr(const float* __restrict__ xp, float* __restrict__ out) {
    __shared__ float red[256];
    int n = blockIdx.x, t = threadIdx.x;
    int h = t >> 5, lane = t & 31;
    int beg = g_off[n], end = g_off[n + 1];
    float ssrc = g_ssrc[n * HEADS + h];

    float den = 0.f, acc = 0.f;
    for (int i = beg; i < end; i++) {
        int s = g_csrc[i];                       // broadcast (uniform) load
        float a = ssrc + g_sdst[s * HEADS + h];
        a = fmaxf(a, NEG_SLOPE * a);             // leaky relu
        a = fminf(a, 80.f);                      // overflow guard (no-op in practice)
        float w = __expf(a);
        den += w;
        acc += w * xp[s * DIM + h * CH + lane];
    }
    float r = acc / den;
    if (MODE == 0) {
        out[n * DIM + t] = (r > 0.f) ? r : (__expf(r) - 1.0f);  // ELU
    } else {
        red[t] = r;
        __syncthreads();
        if (t < CH) {
            float s = 0.f;
#pragma unroll
            for (int hh = 0; hh < HEADS; hh++) s += red[hh * CH + t];
            out[n * CH + t] = s * 0.125f;
        }
    }
}

// ---------------- host launcher ----------------
extern "C" void kernel_launch(void* const* d_in, const int* in_sizes, int n_in,
                              void* d_out, int out_size) {
    const float* x  = (const float*)d_in[0];
    const void*  ei = d_in[1];

    float *xp, *act;
    cudaGetSymbolAddress((void**)&xp, g_xp);
    cudaGetSymbolAddress((void**)&act, g_act);

    // CSR build (shared by both layers)
    k_detect<<<64, 256>>>(ei);
    k_hist<<<(N_EDGES + 255) / 256, 256>>>(ei);
    k_scan<<<1, 1024>>>();
    k_scatter<<<(E_TOT + 255) / 256, 256>>>(ei);

    dim3 gg(DIM / BN, (N_NODES + BM - 1) / BM);

    // ---- layer 0 ----
    k_prep<<<DIM + 1, DIM>>>((const float*)d_in[2], (const float*)d_in[3], (const float*)d_in[4],
                             (const float*)d_in[5], (const float*)d_in[6],
                             (const float*)d_in[7], (const float*)d_in[8],
                             (const float*)d_in[9], (const float*)d_in[10]);
    k_gemm<<<gg, 256>>>(x, xp);
    k_scores<<<N_NODES, 256>>>(xp);
    k_aggr<0><<<N_NODES, 256>>>(xp, act);

    // ---- layer 1 ----
    k_prep<<<DIM + 1, DIM>>>((const float*)d_in[11], (const float*)d_in[12], (const float*)d_in[13],
                             (const float*)d_in[14], (const float*)d_in[15],
                             (const float*)d_in[16], (const float*)d_in[17],
                             (const float*)d_in[18], (const float*)d_in[19]);
    k_gemm<<<gg, 256>>>(act, xp);
    k_scores<<<N_NODES, 256>>>(xp);
    k_aggr<1><<<N_NODES, 256>>>(xp, (float*)d_out);
}